// round 16
// baseline (speedup 1.0000x reference)
#include <cuda_runtime.h>
#include <cuda_bf16.h>
#include <cuda_fp16.h>
#include <math.h>
#include <stdint.h>

#define TT   2048
#define DD   1024
#define NH   16
#define HDIM 64
#define WIN  128
#define PSTR 132
#define SIT  64     // scores i-tile
#define SPAN 192    // scores j-window (64 + 128)
#define IT2  32     // attnv i-tile
#define JT2  160    // attnv max window span (32 + 128)
#define SST  36     // sattn row stride (floats)

// ---------------- scratch (static device globals; no allocation) ----------
__device__ float v_buf[TT * DD];
__device__ float norm_buf[NH * TT];
__device__ float denom_buf[NH * TT];
__device__ float suminv_buf[NH];
__device__ __half p_buf[(size_t)NH * TT * PSTR];   // fp16 score matrix

__device__ __half xh_buf[TT * DD], xl_buf[TT * DD];
__device__ __half oh_buf[TT * DD], ol_buf[TT * DD];
__device__ __half wgh_buf[DD * DD], wvh_buf[DD * DD], woh_buf[DD * DD];
__device__ __nv_bfloat16 gh_buf[TT * DD], gl_buf[TT * DD];

// ---------------- PTX helpers ----------------------------------------------
__device__ __forceinline__ uint32_t s2u(const void* p) {
    uint32_t a;
    asm("{ .reg .u64 t; cvta.to.shared.u64 t, %1; cvt.u32.u64 %0, t; }"
        : "=r"(a) : "l"(p));
    return a;
}
#define CP_ASYNC16(dst, src) \
    asm volatile("cp.async.cg.shared.global [%0], [%1], 16;" :: "r"(dst), "l"(src))
#define CP_COMMIT()  asm volatile("cp.async.commit_group;" ::: "memory")
#define CP_WAIT2()   asm volatile("cp.async.wait_group 2;" ::: "memory")
#define CP_WAIT1()   asm volatile("cp.async.wait_group 1;" ::: "memory")
#define CP_WAIT0()   asm volatile("cp.async.wait_group 0;" ::: "memory")

__device__ __forceinline__ void ldsm_x4(uint32_t& r0, uint32_t& r1,
                                        uint32_t& r2, uint32_t& r3, uint32_t a) {
    asm volatile("ldmatrix.sync.aligned.m8n8.x4.shared.b16 {%0,%1,%2,%3}, [%4];"
                 : "=r"(r0), "=r"(r1), "=r"(r2), "=r"(r3) : "r"(a));
}
__device__ __forceinline__ void mma16816(float* d, const uint32_t* a, const uint32_t* b) {
    asm volatile(
        "mma.sync.aligned.m16n8k16.row.col.f32.bf16.bf16.f32 "
        "{%0,%1,%2,%3}, {%4,%5,%6,%7}, {%8,%9}, {%0,%1,%2,%3};"
        : "+f"(d[0]), "+f"(d[1]), "+f"(d[2]), "+f"(d[3])
        : "r"(a[0]), "r"(a[1]), "r"(a[2]), "r"(a[3]), "r"(b[0]), "r"(b[1]));
}
__device__ __forceinline__ void mma16816h(float* d, const uint32_t* a, const uint32_t* b) {
    asm volatile(
        "mma.sync.aligned.m16n8k16.row.col.f32.f16.f16.f32 "
        "{%0,%1,%2,%3}, {%4,%5,%6,%7}, {%8,%9}, {%0,%1,%2,%3};"
        : "+f"(d[0]), "+f"(d[1]), "+f"(d[2]), "+f"(d[3])
        : "r"(a[0]), "r"(a[1]), "r"(a[2]), "r"(a[3]), "r"(b[0]), "r"(b[1]));
}
__device__ __forceinline__ uint32_t sw64(uint32_t off) {
    return off ^ ((off >> 3) & 0x30u);
}
__device__ __forceinline__ uint32_t sw128(uint32_t off) {
    return off ^ ((off >> 3) & 0x70u);
}

// ---------------- conversions ------------------------------------------------
__device__ __forceinline__ void split_store_h(const float* __restrict__ src,
                                              __half* __restrict__ dh,
                                              __half* __restrict__ dl, int i)
{
    float4 v = ((const float4*)src)[i];
    __half h0 = __float2half_rn(v.x), h1 = __float2half_rn(v.y),
           h2 = __float2half_rn(v.z), h3 = __float2half_rn(v.w);
    __half l0 = __float2half_rn(v.x - __half2float(h0)),
           l1 = __float2half_rn(v.y - __half2float(h1)),
           l2 = __float2half_rn(v.z - __half2float(h2)),
           l3 = __float2half_rn(v.w - __half2float(h3));
    __half2 hp0(h0, h1), hp1(h2, h3), lp0(l0, l1), lp1(l2, l3);
    uint2 uh, ul;
    uh.x = *(unsigned*)&hp0; uh.y = *(unsigned*)&hp1;
    ul.x = *(unsigned*)&lp0; ul.y = *(unsigned*)&lp1;
    ((uint2*)dh)[i] = uh;
    ((uint2*)dl)[i] = ul;
}
__device__ __forceinline__ void single_store_h(const float* __restrict__ src,
                                               __half* __restrict__ dh, int i)
{
    float4 v = ((const float4*)src)[i];
    __half2 hp0(__float2half_rn(v.x), __float2half_rn(v.y));
    __half2 hp1(__float2half_rn(v.z), __float2half_rn(v.w));
    uint2 uh;
    uh.x = *(unsigned*)&hp0; uh.y = *(unsigned*)&hp1;
    ((uint2*)dh)[i] = uh;
}

__global__ void __launch_bounds__(256)
k_conv_all(const float* __restrict__ x,  const float* __restrict__ Wg,
           const float* __restrict__ Wv, const float* __restrict__ Wo)
{
    const int b = blockIdx.x;
    if (b == 0 && threadIdx.x < NH) suminv_buf[threadIdx.x] = 0.f;
    if (b < 1024) {
        const int i = b * 512 + threadIdx.x;
        split_store_h(x, xh_buf, xl_buf, i);
        split_store_h(x, xh_buf, xl_buf, i + 256);
    } else if (b < 1536) {
        const int i = (b - 1024) * 512 + threadIdx.x;
        single_store_h(Wg, wgh_buf, i);
        single_store_h(Wg, wgh_buf, i + 256);
    } else if (b < 2048) {
        const int i = (b - 1536) * 512 + threadIdx.x;
        single_store_h(Wv, wvh_buf, i);
        single_store_h(Wv, wvh_buf, i + 256);
    } else {
        const int i = (b - 2048) * 512 + threadIdx.x;
        single_store_h(Wo, woh_buf, i);
        single_store_h(Wo, woh_buf, i + 256);
    }
}

// ------- fp16 2-product GEMM, CTA tile 128x128 (single-wave grids) ----------
#define KC32   32
#define NC     (DD / KC32)
#define ATSZ   8192
#define STG    (3 * ATSZ)
#define NSTAGE 4
#define SMEM_G (NSTAGE * STG)       // 98304

__device__ __forceinline__ void load_stage(
    const uint4* __restrict__ Ah4, const uint4* __restrict__ Al4,
    const uint4* __restrict__ Bh4,
    uint32_t sb, int slot, int c, int m0, int n0, int tid)
{
    const uint32_t base = sb + slot * STG;
    const int q   = tid & 3;
    const int row = tid >> 2;
#pragma unroll
    for (int t = 0; t < 2; ++t) {
        const int rr = row + t * 64;
        const uint32_t so = sw64((uint32_t)rr * 64u + q * 16u);
        const size_t goA = (size_t)(m0 + rr) * (DD / 8) + c * 4 + q;
        const size_t goB = (size_t)(n0 + rr) * (DD / 8) + c * 4 + q;
        CP_ASYNC16(base + so,            Ah4 + goA);
        CP_ASYNC16(base + ATSZ + so,     Al4 + goA);
        CP_ASYNC16(base + 2 * ATSZ + so, Bh4 + goB);
    }
}

__device__ __forceinline__ void gemm_core(
    const uint4* __restrict__ Ah4, const uint4* __restrict__ Al4,
    const uint4* __restrict__ Bh4,
    const float* __restrict__ bias, float* __restrict__ C, bool doNorm)
{
    extern __shared__ char smem[];
    __shared__ float ssrow[2][128];
    const uint32_t sb = s2u(smem);
    const int tid  = threadIdx.x;
    const int wid  = tid >> 5;
    const int lane = tid & 31;
    const int n0 = blockIdx.x * 128, m0 = blockIdx.y * 128;

    const int wm = wid >> 1;
    const int wn = wid & 1;

    const int r  = lane & 7;
    const int md = lane >> 3;
    const int rowA = wm * 32 + (md & 1) * 8 + r;
    const uint32_t bA = (md >> 1) * 16;
    const int rowB = wn * 64 + (md >> 1) * 8 + r;
    const uint32_t bB = (md & 1) * 16;

    if (doNorm) ((float*)ssrow)[tid] = 0.f;

    float acc[2][8][4];
#pragma unroll
    for (int f = 0; f < 2; ++f)
#pragma unroll
        for (int j = 0; j < 8; ++j)
#pragma unroll
            for (int e = 0; e < 4; ++e) acc[f][j][e] = 0.f;

    load_stage(Ah4, Al4, Bh4, sb, 0, 0, m0, n0, tid); CP_COMMIT();
    load_stage(Ah4, Al4, Bh4, sb, 1, 1, m0, n0, tid); CP_COMMIT();
    load_stage(Ah4, Al4, Bh4, sb, 2, 2, m0, n0, tid); CP_COMMIT();

#pragma unroll 1
    for (int c = 0; c < NC; ++c) {
        const int rem = NC - 1 - c;
        if (rem >= 2) CP_WAIT2(); else if (rem == 1) CP_WAIT1(); else CP_WAIT0();
        __syncthreads();

        const uint32_t base = sb + (c & 3) * STG;
        const uint32_t stAh = base;
        const uint32_t stAl = base + ATSZ;
        const uint32_t stBh = base + 2 * ATSZ;

#pragma unroll
        for (int ks = 0; ks < 2; ++ks) {
            const uint32_t kb = ks * 32;
            uint32_t ah[2][4], al[2][4];
#pragma unroll
            for (int f = 0; f < 2; ++f) {
                const uint32_t off = sw64((uint32_t)(rowA + f * 16) * 64u + kb + bA);
                ldsm_x4(ah[f][0], ah[f][1], ah[f][2], ah[f][3], stAh + off);
                ldsm_x4(al[f][0], al[f][1], al[f][2], al[f][3], stAl + off);
            }
            uint32_t bh[8][2];
#pragma unroll
            for (int p = 0; p < 4; ++p) {
                const uint32_t off = sw64((uint32_t)(rowB + p * 16) * 64u + kb + bB);
                ldsm_x4(bh[2*p][0], bh[2*p][1], bh[2*p+1][0], bh[2*p+1][1], stBh + off);
            }
#pragma unroll
            for (int f = 0; f < 2; ++f)
#pragma unroll
                for (int j = 0; j < 8; ++j) {
                    mma16816h(acc[f][j], ah[f], bh[j]);
                    mma16816h(acc[f][j], al[f], bh[j]);
                }
        }
        if (c + 3 < NC) {
            load_stage(Ah4, Al4, Bh4, sb, (c + 3) & 3, c + 3, m0, n0, tid);
            CP_COMMIT();
        }
    }

    // epilogue
#pragma unroll
    for (int f = 0; f < 2; ++f) {
        const int grow = m0 + wm * 32 + f * 16 + (lane >> 2);
        float ss0 = 0.f, ss1 = 0.f;
#pragma unroll
        for (int j = 0; j < 8; ++j) {
            const int col = n0 + wn * 64 + j * 8 + (lane & 3) * 2;
            const float2 bb = *(const float2*)(bias + col);
            float2 o0 = make_float2(acc[f][j][0] + bb.x, acc[f][j][1] + bb.y);
            float2 o1 = make_float2(acc[f][j][2] + bb.x, acc[f][j][3] + bb.y);
            if (doNorm) {
                const size_t p0 = ((size_t)grow * DD + col) >> 1;
                const size_t p1 = ((size_t)(grow + 8) * DD + col) >> 1;
                __nv_bfloat16 h00 = __float2bfloat16(o0.x), h01 = __float2bfloat16(o0.y);
                __nv_bfloat16 h10 = __float2bfloat16(o1.x), h11 = __float2bfloat16(o1.y);
                __nv_bfloat16 l00 = __float2bfloat16(o0.x - __bfloat162float(h00));
                __nv_bfloat16 l01 = __float2bfloat16(o0.y - __bfloat162float(h01));
                __nv_bfloat16 l10 = __float2bfloat16(o1.x - __bfloat162float(h10));
                __nv_bfloat16 l11 = __float2bfloat16(o1.y - __bfloat162float(h11));
                ((__nv_bfloat162*)gh_buf)[p0] = __nv_bfloat162(h00, h01);
                ((__nv_bfloat162*)gl_buf)[p0] = __nv_bfloat162(l00, l01);
                ((__nv_bfloat162*)gh_buf)[p1] = __nv_bfloat162(h10, h11);
                ((__nv_bfloat162*)gl_buf)[p1] = __nv_bfloat162(l10, l11);
                ss0 = fmaf(o0.x, o0.x, fmaf(o0.y, o0.y, ss0));
                ss1 = fmaf(o1.x, o1.x, fmaf(o1.y, o1.y, ss1));
            } else {
                float* c0 = C + (size_t)grow * DD;
                *(float2*)(c0 + col) = o0;
                *(float2*)(c0 + 8 * DD + col) = o1;
            }
        }
        if (doNorm) {
            ss0 += __shfl_xor_sync(0xffffffffu, ss0, 1);
            ss0 += __shfl_xor_sync(0xffffffffu, ss0, 2);
            ss1 += __shfl_xor_sync(0xffffffffu, ss1, 1);
            ss1 += __shfl_xor_sync(0xffffffffu, ss1, 2);
            if ((lane & 3) == 0) {
                const int l0 = wm * 32 + f * 16 + (lane >> 2);
                atomicAdd(&ssrow[wn][l0], ss0);
                atomicAdd(&ssrow[wn][l0 + 8], ss1);
            }
        }
    }
    if (doNorm) {
        __syncthreads();
        const int h = (n0 >> 6) + (tid >> 7);
        norm_buf[h * TT + m0 + (tid & 127)] = sqrtf(ssrow[tid >> 7][tid & 127]);
    }
}

__global__ void __launch_bounds__(256, 2)
k_gemm_gv(const float* __restrict__ bg, const float* __restrict__ bv)
{
    if (blockIdx.z == 0)
        gemm_core((const uint4*)xh_buf, (const uint4*)xl_buf,
                  (const uint4*)wgh_buf, bg, nullptr, true);
    else
        gemm_core((const uint4*)xh_buf, (const uint4*)xl_buf,
                  (const uint4*)wvh_buf, bv, v_buf, false);
}

__global__ void __launch_bounds__(256, 2)
k_gemm_o(const float* __restrict__ bo, float* __restrict__ out)
{
    gemm_core((const uint4*)oh_buf, (const uint4*)ol_buf,
              (const uint4*)woh_buf, bo, out, false);
}

// ---------------- MMA banded scores (bf16 3-product) -------------------------
#define WTSZ   (SPAN * 128)
#define SMEM_S (2 * WTSZ)

__global__ void __launch_bounds__(256)
k_scores_mma()
{
    extern __shared__ char smem[];
    __shared__ float nwin[SPAN];
    __shared__ float rowsum[SIT];
    __shared__ float sinv[SIT];

    const uint32_t sbH = s2u(smem);
    const uint32_t sbL = sbH + WTSZ;
    const int tid  = threadIdx.x;
    const int wid  = tid >> 5;
    const int lane = tid & 31;
    const int i0 = blockIdx.x * SIT;
    const int h  = blockIdx.y;

    const int jstart0 = (i0 > WIN) ? (i0 - WIN) : 0;
    const int qbase   = i0 - jstart0;

    const uint4* gh4 = (const uint4*)gh_buf;
    const uint4* gl4 = (const uint4*)gl_buf;
#pragma unroll
    for (int t = 0; t < 6; ++t) {
        const int idx = t * 256 + tid;
        const int row = idx >> 3;
        const int q   = idx & 7;
        const uint32_t d = sw128((uint32_t)row * 128u + q * 16u);
        const size_t g = (size_t)(jstart0 + row) * (DD / 8) + h * 8 + q;
        CP_ASYNC16(sbH + d, gh4 + g);
        CP_ASYNC16(sbL + d, gl4 + g);
    }
    CP_COMMIT();
    if (tid < SPAN) nwin[tid] = norm_buf[h * TT + jstart0 + tid];
    if (tid < SIT) rowsum[tid] = 0.f;
    CP_WAIT0();
    __syncthreads();

    const int wm = wid >> 1;
    const int wn = wid & 1;

    const int r  = lane & 7;
    const int md = lane >> 3;
    const int arow  = qbase + wm * 16 + (md & 1) * 8 + r;
    const uint32_t abyte = (md >> 1) * 16;
    const int brow0 = wn * 96 + (md >> 1) * 8 + r;
    const uint32_t bbyte = (md & 1) * 16;

    float acc[12][4];
#pragma unroll
    for (int nt = 0; nt < 12; ++nt)
#pragma unroll
        for (int e = 0; e < 4; ++e) acc[nt][e] = 0.f;

#pragma unroll
    for (int ks = 0; ks < 4; ++ks) {
        const uint32_t kb = ks * 32;
        uint32_t ah[4], al[4];
        const uint32_t aoff = sw128((uint32_t)arow * 128u + kb + abyte);
        ldsm_x4(ah[0], ah[1], ah[2], ah[3], sbH + aoff);
        ldsm_x4(al[0], al[1], al[2], al[3], sbL + aoff);
#pragma unroll
        for (int bt = 0; bt < 6; ++bt) {
            uint32_t bh[2][2], bl[2][2];
            const uint32_t boff = sw128((uint32_t)(brow0 + bt * 16) * 128u + kb + bbyte);
            ldsm_x4(bh[0][0], bh[0][1], bh[1][0], bh[1][1], sbH + boff);
            ldsm_x4(bl[0][0], bl[0][1], bl[1][0], bl[1][1], sbL + boff);
#pragma unroll
            for (int p = 0; p < 2; ++p) {
                mma16816(acc[2*bt + p], ah, bh[p]);
                mma16816(acc[2*bt + p], ah, bl[p]);
                mma16816(acc[2*bt + p], al, bh[p]);
            }
        }
    }

    const int quad = lane >> 2;
    const int cp2  = (lane & 3) * 2;
    const int gi0 = i0 + wm * 16 + quad;
    const int gi1 = gi0 + 8;
    const float ni0 = nwin[qbase + wm * 16 + quad];
    const float ni1 = nwin[qbase + wm * 16 + quad + 8];
    const int off0 = (gi0 > WIN) ? (gi0 - WIN) : 0;
    const int off1 = (gi1 > WIN) ? (gi1 - WIN) : 0;
    __half* pr0 = p_buf + (size_t)(h * TT + gi0) * PSTR;
    __half* pr1 = p_buf + (size_t)(h * TT + gi1) * PSTR;
    float ps0 = 0.f, ps1 = 0.f;

#pragma unroll
    for (int nt = 0; nt < 12; ++nt) {
        const int jl = wn * 96 + nt * 8 + cp2;
        const int jg = jstart0 + jl;
        const float nj0 = nwin[jl];
        const float nj1 = nwin[jl + 1];
#pragma unroll
        for (int e = 0; e < 4; ++e) {
            const int  jj = jg + (e & 1);
            const float nj = (e & 1) ? nj1 : nj0;
            const int  gi  = (e >> 1) ? gi1 : gi0;
            const float ni = (e >> 1) ? ni1 : ni0;
            const int  off = (e >> 1) ? off1 : off0;
            if (jj <= gi && jj >= off) {
                float c = acc[nt][e] / (ni * nj + 1e-8f);
                if (c != c) c = 0.f;
                float p = (c + 1.f) * 0.5f;
                ((e >> 1) ? pr1 : pr0)[jj - off] = __float2half_rn(p);
                if (e >> 1) ps1 += p; else ps0 += p;
            }
        }
    }

    ps0 += __shfl_xor_sync(0xffffffffu, ps0, 1);
    ps0 += __shfl_xor_sync(0xffffffffu, ps0, 2);
    ps1 += __shfl_xor_sync(0xffffffffu, ps1, 1);
    ps1 += __shfl_xor_sync(0xffffffffu, ps1, 2);
    if ((lane & 3) == 0) {
        atomicAdd(&rowsum[wm * 16 + quad], ps0);
        atomicAdd(&rowsum[wm * 16 + quad + 8], ps1);
    }
    __syncthreads();

    if (tid < SIT) {
        const int i   = i0 + tid;
        const int cnt = i - ((i > WIN) ? (i - WIN) : 0) + 1;
        float gm = (rowsum[tid] + 0.5f * (float)(TT - cnt)) * (1.f / (float)TT);
        float dn = gm + 0.5f;
        denom_buf[h * TT + i] = dn;
        sinv[tid] = 1.f / dn;
    }
    __syncthreads();
    if (tid < 32) {
        float s = sinv[tid] + sinv[tid + 32];
#pragma unroll
        for (int o = 16; o > 0; o >>= 1) s += __shfl_xor_sync(0xffffffffu, s, o);
        if (tid == 0) atomicAdd(&suminv_buf[h], s);
    }
}

// -------- softmax + attn@v: 32 rows/block, 512 threads, overlapped ----------
#define ATTN_SMEM (JT2 * HDIM * 4 + JT2 * SST * 4 + 128)

__global__ void __launch_bounds__(512)
k_attnv()
{
    extern __shared__ char dynsm[];
    float (*vw)[HDIM]   = (float(*)[HDIM])dynsm;                   // [160][64]
    float (*sattn)[SST] = (float(*)[SST])(dynsm + JT2 * HDIM * 4); // [160][36]
    float* invs = (float*)(dynsm + JT2 * HDIM * 4 + JT2 * SST * 4); // [32]

    const int i0  = blockIdx.x * IT2;
    const int h   = blockIdx.y;
    const int tid = threadIdx.x;
    const int wid = tid >> 5;          // 0..15
    const int lane = tid & 31;

    const int jstart0 = (i0 > WIN) ? (i0 - WIN) : 0;
    const int span    = (i0 + IT2 - 1) - jstart0 + 1;     // <= 160

    // async v-window load — overlapped with phase A
    {
        const uint32_t vw_base = s2u(dynsm);
        const float4* v4 = (const float4*)v_buf;
        for (int idx = tid; idx < span * 16; idx += 512) {
            const int jj = idx >> 4;
            const int q  = idx & 15;
            CP_ASYNC16(vw_base + (uint32_t)idx * 16u,
                       v4 + (size_t)(jstart0 + jj) * (DD / 4) + h * (HDIM / 4) + q);
        }
        CP_COMMIT();
    }

    // phase A (single pass, no max): warp wid handles rows wid and wid+16
#pragma unroll
    for (int rr = 0; rr < 2; ++rr) {
        const int w = wid + rr * 16;
        const int i = i0 + w;
        const size_t row = (size_t)h * TT + i;
        const float fit  = 1.f / (denom_buf[row] * suminv_buf[h]);
        const int off = ((i > WIN) ? (i - WIN) : 0) - jstart0;
        const int wi  = i - jstart0;

        float ss = 0.f;
        for (int q = lane; q < JT2; q += 32) {
            const bool in = (q >= off) && (q <= wi);
            float e = in ? __expf(fit * __half2float(p_buf[row * PSTR + (q - off)])) : 0.f;
            sattn[q][w] = e;
            ss += e;
        }
#pragma unroll
        for (int o = 16; o > 0; o >>= 1) ss += __shfl_xor_sync(0xffffffffu, ss, o);
        if (lane == 0) invs[w] = 1.f / ss;
    }
    CP_WAIT0();
    __syncthreads();

    // phase B: thread = (d, grp of 8); each grp handles rows grp*4..grp*4+3
    {
        const int d   = tid & 63;
        const int grp = tid >> 6;          // 0..7
        float a0 = 0.f, a1 = 0.f, a2 = 0.f, a3 = 0.f;
        float b0 = 0.f, b1 = 0.f, b2 = 0.f, b3 = 0.f;
        int jj = 0;
        for (; jj + 1 < span; jj += 2) {
            const float v0 = vw[jj][d];
            const float v1 = vw[jj + 1][d];
            const float4 s0 = *(const float4*)&sattn[jj][grp * 4];
            const float4 s1 = *(const float4*)&sattn[jj + 1][grp * 4];
            a0 = fmaf(s0.x, v0, a0);  a1 = fmaf(s0.y, v0, a1);
            a2 = fmaf(s0.z, v0, a2);  a3 = fmaf(s0.w, v0, a3);
            b0 = fmaf(s1.x, v1, b0);  b1 = fmaf(s1.y, v1, b1);
            b2 = fmaf(s1.z, v1, b2);  b3 = fmaf(s1.w, v1, b3);
        }
        if (jj < span) {
            const float v0 = vw[jj][d];
            const float4 s0 = *(const float4*)&sattn[jj][grp * 4];
            a0 = fmaf(s0.x, v0, a0);  a1 = fmaf(s0.y, v0, a1);
            a2 = fmaf(s0.z, v0, a2);  a3 = fmaf(s0.w, v0, a3);
        }
        a0 += b0; a1 += b1; a2 += b2; a3 += b3;

        const float r0 = a0 * invs[grp * 4 + 0];
        const float r1 = a1 * invs[grp * 4 + 1];
        const float r2 = a2 * invs[grp * 4 + 2];
        const float r3 = a3 * invs[grp * 4 + 3];
        const size_t base = (size_t)(i0 + grp * 4) * DD + h * HDIM + d;
#pragma unroll
        for (int rI = 0; rI < 4; ++rI) {
            const float val = (rI == 0) ? r0 : (rI == 1) ? r1 : (rI == 2) ? r2 : r3;
            const size_t idx = base + (size_t)rI * DD;
            __half hv = __float2half_rn(val);
            __half lv = __float2half_rn(val - __half2float(hv));
            oh_buf[idx] = hv;
            ol_buf[idx] = lv;
        }
    }
}

// ---------------- launch ---------------------------------------------------
extern "C" void kernel_launch(void* const* d_in, const int* in_sizes, int n_in,
                              void* d_out, int out_size)
{
    const float* x  = (const float*)d_in[0];
    const float* Wg = (const float*)d_in[1];
    const float* bg = (const float*)d_in[2];
    const float* Wv = (const float*)d_in[3];
    const float* bv = (const float*)d_in[4];
    const float* Wo = (const float*)d_in[5];
    const float* bo = (const float*)d_in[6];
    float* out = (float*)d_out;

    cudaFuncSetAttribute(k_gemm_gv,   cudaFuncAttributeMaxDynamicSharedMemorySize, SMEM_G);
    cudaFuncSetAttribute(k_gemm_o,    cudaFuncAttributeMaxDynamicSharedMemorySize, SMEM_G);
    cudaFuncSetAttribute(k_scores_mma,cudaFuncAttributeMaxDynamicSharedMemorySize, SMEM_S);
    cudaFuncSetAttribute(k_attnv,     cudaFuncAttributeMaxDynamicSharedMemorySize, ATTN_SMEM);

    k_conv_all<<<2560, 256>>>(x, Wg, Wv, Wo);                 // #1

    dim3 gemm_gv(DD / 128, TT / 128, 2);                      // 256 CTAs = 1 wave
    k_gemm_gv<<<gemm_gv, 256, SMEM_G>>>(bg, bv);              // #2

    dim3 sc_grid(TT / SIT, NH);
    k_scores_mma<<<sc_grid, 256, SMEM_S>>>();                 // #3

    dim3 av_grid(TT / IT2, NH);                               // 1024 blocks
    k_attnv<<<av_grid, 512, ATTN_SMEM>>>();                   // #4 (ncu slot)

    dim3 gemm_o(DD / 128, TT / 128, 1);                       // 128 CTAs = 1 wave
    k_gemm_o<<<gemm_o, 256, SMEM_G>>>(bo, out);               // #5
}

// round 17
// speedup vs baseline: 1.0611x; 1.0611x over previous
#include <cuda_runtime.h>
#include <cuda_bf16.h>
#include <cuda_fp16.h>
#include <math.h>
#include <stdint.h>

#define TT   2048
#define DD   1024
#define NH   16
#define HDIM 64
#define WIN  128
#define PSTR 132
#define SIT  64     // scores i-tile
#define SPAN 192    // scores j-window (64 + 128)
#define IT   16     // attnv i-tile
#define KP   144    // attnv padded K (max span for IT=16)
#define VSTR 88     // v smem row stride (halfs); 12r mod 32 distinct
#define ASTR 152    // t/mask smem row stride (halfs)

// ---------------- scratch (static device globals; no allocation) ----------
__device__ float v_buf[TT * DD];
__device__ float norm_buf[NH * TT];
__device__ float denom_buf[NH * TT];
__device__ float suminv_buf[NH];
__device__ __half p_buf[(size_t)NH * TT * PSTR];   // fp16 score matrix

__device__ __half xh_buf[TT * DD], xl_buf[TT * DD];
__device__ __half oh_buf[TT * DD], ol_buf[TT * DD];
__device__ __half wgh_buf[DD * DD], wvh_buf[DD * DD], woh_buf[DD * DD];
__device__ __nv_bfloat16 gh_buf[TT * DD], gl_buf[TT * DD];

// ---------------- PTX helpers ----------------------------------------------
__device__ __forceinline__ uint32_t s2u(const void* p) {
    uint32_t a;
    asm("{ .reg .u64 t; cvta.to.shared.u64 t, %1; cvt.u32.u64 %0, t; }"
        : "=r"(a) : "l"(p));
    return a;
}
#define CP_ASYNC16(dst, src) \
    asm volatile("cp.async.cg.shared.global [%0], [%1], 16;" :: "r"(dst), "l"(src))
#define CP_COMMIT()  asm volatile("cp.async.commit_group;" ::: "memory")
#define CP_WAIT2()   asm volatile("cp.async.wait_group 2;" ::: "memory")
#define CP_WAIT1()   asm volatile("cp.async.wait_group 1;" ::: "memory")
#define CP_WAIT0()   asm volatile("cp.async.wait_group 0;" ::: "memory")

__device__ __forceinline__ void ldsm_x4(uint32_t& r0, uint32_t& r1,
                                        uint32_t& r2, uint32_t& r3, uint32_t a) {
    asm volatile("ldmatrix.sync.aligned.m8n8.x4.shared.b16 {%0,%1,%2,%3}, [%4];"
                 : "=r"(r0), "=r"(r1), "=r"(r2), "=r"(r3) : "r"(a));
}
__device__ __forceinline__ void ldsm_x2_trans(uint32_t& r0, uint32_t& r1, uint32_t a) {
    asm volatile("ldmatrix.sync.aligned.m8n8.x2.trans.shared.b16 {%0,%1}, [%2];"
                 : "=r"(r0), "=r"(r1) : "r"(a));
}
__device__ __forceinline__ void mma16816(float* d, const uint32_t* a, const uint32_t* b) {
    asm volatile(
        "mma.sync.aligned.m16n8k16.row.col.f32.bf16.bf16.f32 "
        "{%0,%1,%2,%3}, {%4,%5,%6,%7}, {%8,%9}, {%0,%1,%2,%3};"
        : "+f"(d[0]), "+f"(d[1]), "+f"(d[2]), "+f"(d[3])
        : "r"(a[0]), "r"(a[1]), "r"(a[2]), "r"(a[3]), "r"(b[0]), "r"(b[1]));
}
__device__ __forceinline__ void mma16816h(float* d, const uint32_t* a, const uint32_t* b) {
    asm volatile(
        "mma.sync.aligned.m16n8k16.row.col.f32.f16.f16.f32 "
        "{%0,%1,%2,%3}, {%4,%5,%6,%7}, {%8,%9}, {%0,%1,%2,%3};"
        : "+f"(d[0]), "+f"(d[1]), "+f"(d[2]), "+f"(d[3])
        : "r"(a[0]), "r"(a[1]), "r"(a[2]), "r"(a[3]), "r"(b[0]), "r"(b[1]));
}
__device__ __forceinline__ uint32_t sw64(uint32_t off) {
    return off ^ ((off >> 3) & 0x30u);
}
__device__ __forceinline__ uint32_t sw128(uint32_t off) {
    return off ^ ((off >> 3) & 0x70u);
}

// ---------------- conversions ------------------------------------------------
__device__ __forceinline__ void split_store_h(const float* __restrict__ src,
                                              __half* __restrict__ dh,
                                              __half* __restrict__ dl, int i)
{
    float4 v = ((const float4*)src)[i];
    __half h0 = __float2half_rn(v.x), h1 = __float2half_rn(v.y),
           h2 = __float2half_rn(v.z), h3 = __float2half_rn(v.w);
    __half l0 = __float2half_rn(v.x - __half2float(h0)),
           l1 = __float2half_rn(v.y - __half2float(h1)),
           l2 = __float2half_rn(v.z - __half2float(h2)),
           l3 = __float2half_rn(v.w - __half2float(h3));
    __half2 hp0(h0, h1), hp1(h2, h3), lp0(l0, l1), lp1(l2, l3);
    uint2 uh, ul;
    uh.x = *(unsigned*)&hp0; uh.y = *(unsigned*)&hp1;
    ul.x = *(unsigned*)&lp0; ul.y = *(unsigned*)&lp1;
    ((uint2*)dh)[i] = uh;
    ((uint2*)dl)[i] = ul;
}
__device__ __forceinline__ void single_store_h(const float* __restrict__ src,
                                               __half* __restrict__ dh, int i)
{
    float4 v = ((const float4*)src)[i];
    __half2 hp0(__float2half_rn(v.x), __float2half_rn(v.y));
    __half2 hp1(__float2half_rn(v.z), __float2half_rn(v.w));
    uint2 uh;
    uh.x = *(unsigned*)&hp0; uh.y = *(unsigned*)&hp1;
    ((uint2*)dh)[i] = uh;
}

__global__ void __launch_bounds__(256)
k_conv_all(const float* __restrict__ x,  const float* __restrict__ Wg,
           const float* __restrict__ Wv, const float* __restrict__ Wo)
{
    const int b = blockIdx.x;
    if (b == 0 && threadIdx.x < NH) suminv_buf[threadIdx.x] = 0.f;
    if (b < 1024) {
        const int i = b * 512 + threadIdx.x;
        split_store_h(x, xh_buf, xl_buf, i);
        split_store_h(x, xh_buf, xl_buf, i + 256);
    } else if (b < 1536) {
        const int i = (b - 1024) * 512 + threadIdx.x;
        single_store_h(Wg, wgh_buf, i);
        single_store_h(Wg, wgh_buf, i + 256);
    } else if (b < 2048) {
        const int i = (b - 1536) * 512 + threadIdx.x;
        single_store_h(Wv, wvh_buf, i);
        single_store_h(Wv, wvh_buf, i + 256);
    } else {
        const int i = (b - 2048) * 512 + threadIdx.x;
        single_store_h(Wo, woh_buf, i);
        single_store_h(Wo, woh_buf, i + 256);
    }
}

// ------- fp16 2-product GEMM, CTA tile 128x128 (single-wave grids) ----------
#define KC32   32
#define NC     (DD / KC32)
#define ATSZ   8192
#define STG    (3 * ATSZ)
#define NSTAGE 4
#define SMEM_G (NSTAGE * STG)       // 98304

__device__ __forceinline__ void load_stage(
    const uint4* __restrict__ Ah4, const uint4* __restrict__ Al4,
    const uint4* __restrict__ Bh4,
    uint32_t sb, int slot, int c, int m0, int n0, int tid)
{
    const uint32_t base = sb + slot * STG;
    const int q   = tid & 3;
    const int row = tid >> 2;
#pragma unroll
    for (int t = 0; t < 2; ++t) {
        const int rr = row + t * 64;
        const uint32_t so = sw64((uint32_t)rr * 64u + q * 16u);
        const size_t goA = (size_t)(m0 + rr) * (DD / 8) + c * 4 + q;
        const size_t goB = (size_t)(n0 + rr) * (DD / 8) + c * 4 + q;
        CP_ASYNC16(base + so,            Ah4 + goA);
        CP_ASYNC16(base + ATSZ + so,     Al4 + goA);
        CP_ASYNC16(base + 2 * ATSZ + so, Bh4 + goB);
    }
}

__device__ __forceinline__ void gemm_core(
    const uint4* __restrict__ Ah4, const uint4* __restrict__ Al4,
    const uint4* __restrict__ Bh4,
    const float* __restrict__ bias, float* __restrict__ C, bool doNorm)
{
    extern __shared__ char smem[];
    __shared__ float ssrow[2][128];
    const uint32_t sb = s2u(smem);
    const int tid  = threadIdx.x;
    const int wid  = tid >> 5;
    const int lane = tid & 31;
    const int n0 = blockIdx.x * 128, m0 = blockIdx.y * 128;

    const int wm = wid >> 1;
    const int wn = wid & 1;

    const int r  = lane & 7;
    const int md = lane >> 3;
    const int rowA = wm * 32 + (md & 1) * 8 + r;
    const uint32_t bA = (md >> 1) * 16;
    const int rowB = wn * 64 + (md >> 1) * 8 + r;
    const uint32_t bB = (md & 1) * 16;

    if (doNorm) ((float*)ssrow)[tid] = 0.f;

    float acc[2][8][4];
#pragma unroll
    for (int f = 0; f < 2; ++f)
#pragma unroll
        for (int j = 0; j < 8; ++j)
#pragma unroll
            for (int e = 0; e < 4; ++e) acc[f][j][e] = 0.f;

    load_stage(Ah4, Al4, Bh4, sb, 0, 0, m0, n0, tid); CP_COMMIT();
    load_stage(Ah4, Al4, Bh4, sb, 1, 1, m0, n0, tid); CP_COMMIT();
    load_stage(Ah4, Al4, Bh4, sb, 2, 2, m0, n0, tid); CP_COMMIT();

#pragma unroll 1
    for (int c = 0; c < NC; ++c) {
        const int rem = NC - 1 - c;
        if (rem >= 2) CP_WAIT2(); else if (rem == 1) CP_WAIT1(); else CP_WAIT0();
        __syncthreads();

        const uint32_t base = sb + (c & 3) * STG;
        const uint32_t stAh = base;
        const uint32_t stAl = base + ATSZ;
        const uint32_t stBh = base + 2 * ATSZ;

#pragma unroll
        for (int ks = 0; ks < 2; ++ks) {
            const uint32_t kb = ks * 32;
            uint32_t ah[2][4], al[2][4];
#pragma unroll
            for (int f = 0; f < 2; ++f) {
                const uint32_t off = sw64((uint32_t)(rowA + f * 16) * 64u + kb + bA);
                ldsm_x4(ah[f][0], ah[f][1], ah[f][2], ah[f][3], stAh + off);
                ldsm_x4(al[f][0], al[f][1], al[f][2], al[f][3], stAl + off);
            }
            uint32_t bh[8][2];
#pragma unroll
            for (int p = 0; p < 4; ++p) {
                const uint32_t off = sw64((uint32_t)(rowB + p * 16) * 64u + kb + bB);
                ldsm_x4(bh[2*p][0], bh[2*p][1], bh[2*p+1][0], bh[2*p+1][1], stBh + off);
            }
#pragma unroll
            for (int f = 0; f < 2; ++f)
#pragma unroll
                for (int j = 0; j < 8; ++j) {
                    mma16816h(acc[f][j], ah[f], bh[j]);
                    mma16816h(acc[f][j], al[f], bh[j]);
                }
        }
        if (c + 3 < NC) {
            load_stage(Ah4, Al4, Bh4, sb, (c + 3) & 3, c + 3, m0, n0, tid);
            CP_COMMIT();
        }
    }

    // epilogue
#pragma unroll
    for (int f = 0; f < 2; ++f) {
        const int grow = m0 + wm * 32 + f * 16 + (lane >> 2);
        float ss0 = 0.f, ss1 = 0.f;
#pragma unroll
        for (int j = 0; j < 8; ++j) {
            const int col = n0 + wn * 64 + j * 8 + (lane & 3) * 2;
            const float2 bb = *(const float2*)(bias + col);
            float2 o0 = make_float2(acc[f][j][0] + bb.x, acc[f][j][1] + bb.y);
            float2 o1 = make_float2(acc[f][j][2] + bb.x, acc[f][j][3] + bb.y);
            if (doNorm) {
                const size_t p0 = ((size_t)grow * DD + col) >> 1;
                const size_t p1 = ((size_t)(grow + 8) * DD + col) >> 1;
                __nv_bfloat16 h00 = __float2bfloat16(o0.x), h01 = __float2bfloat16(o0.y);
                __nv_bfloat16 h10 = __float2bfloat16(o1.x), h11 = __float2bfloat16(o1.y);
                __nv_bfloat16 l00 = __float2bfloat16(o0.x - __bfloat162float(h00));
                __nv_bfloat16 l01 = __float2bfloat16(o0.y - __bfloat162float(h01));
                __nv_bfloat16 l10 = __float2bfloat16(o1.x - __bfloat162float(h10));
                __nv_bfloat16 l11 = __float2bfloat16(o1.y - __bfloat162float(h11));
                ((__nv_bfloat162*)gh_buf)[p0] = __nv_bfloat162(h00, h01);
                ((__nv_bfloat162*)gl_buf)[p0] = __nv_bfloat162(l00, l01);
                ((__nv_bfloat162*)gh_buf)[p1] = __nv_bfloat162(h10, h11);
                ((__nv_bfloat162*)gl_buf)[p1] = __nv_bfloat162(l10, l11);
                ss0 = fmaf(o0.x, o0.x, fmaf(o0.y, o0.y, ss0));
                ss1 = fmaf(o1.x, o1.x, fmaf(o1.y, o1.y, ss1));
            } else {
                float* c0 = C + (size_t)grow * DD;
                *(float2*)(c0 + col) = o0;
                *(float2*)(c0 + 8 * DD + col) = o1;
            }
        }
        if (doNorm) {
            ss0 += __shfl_xor_sync(0xffffffffu, ss0, 1);
            ss0 += __shfl_xor_sync(0xffffffffu, ss0, 2);
            ss1 += __shfl_xor_sync(0xffffffffu, ss1, 1);
            ss1 += __shfl_xor_sync(0xffffffffu, ss1, 2);
            if ((lane & 3) == 0) {
                const int l0 = wm * 32 + f * 16 + (lane >> 2);
                atomicAdd(&ssrow[wn][l0], ss0);
                atomicAdd(&ssrow[wn][l0 + 8], ss1);
            }
        }
    }
    if (doNorm) {
        __syncthreads();
        const int h = (n0 >> 6) + (tid >> 7);
        norm_buf[h * TT + m0 + (tid & 127)] = sqrtf(ssrow[tid >> 7][tid & 127]);
    }
}

__global__ void __launch_bounds__(256, 2)
k_gemm_gv(const float* __restrict__ bg, const float* __restrict__ bv)
{
    if (blockIdx.z == 0)
        gemm_core((const uint4*)xh_buf, (const uint4*)xl_buf,
                  (const uint4*)wgh_buf, bg, nullptr, true);
    else
        gemm_core((const uint4*)xh_buf, (const uint4*)xl_buf,
                  (const uint4*)wvh_buf, bv, v_buf, false);
}

__global__ void __launch_bounds__(256, 2)
k_gemm_o(const float* __restrict__ bo, float* __restrict__ out)
{
    gemm_core((const uint4*)oh_buf, (const uint4*)ol_buf,
              (const uint4*)woh_buf, bo, out, false);
}

// ---------------- MMA banded scores (bf16 3-product) -------------------------
#define WTSZ   (SPAN * 128)
#define SMEM_S (2 * WTSZ)

__global__ void __launch_bounds__(256)
k_scores_mma()
{
    extern __shared__ char smem[];
    __shared__ float nwin[SPAN];
    __shared__ float rowsum[SIT];
    __shared__ float sinv[SIT];

    const uint32_t sbH = s2u(smem);
    const uint32_t sbL = sbH + WTSZ;
    const int tid  = threadIdx.x;
    const int wid  = tid >> 5;
    const int lane = tid & 31;
    const int i0 = blockIdx.x * SIT;
    const int h  = blockIdx.y;

    const int jstart0 = (i0 > WIN) ? (i0 - WIN) : 0;
    const int qbase   = i0 - jstart0;

    const uint4* gh4 = (const uint4*)gh_buf;
    const uint4* gl4 = (const uint4*)gl_buf;
#pragma unroll
    for (int t = 0; t < 6; ++t) {
        const int idx = t * 256 + tid;
        const int row = idx >> 3;
        const int q   = idx & 7;
        const uint32_t d = sw128((uint32_t)row * 128u + q * 16u);
        const size_t g = (size_t)(jstart0 + row) * (DD / 8) + h * 8 + q;
        CP_ASYNC16(sbH + d, gh4 + g);
        CP_ASYNC16(sbL + d, gl4 + g);
    }
    CP_COMMIT();
    if (tid < SPAN) nwin[tid] = norm_buf[h * TT + jstart0 + tid];
    if (tid < SIT) rowsum[tid] = 0.f;
    CP_WAIT0();
    __syncthreads();

    const int wm = wid >> 1;
    const int wn = wid & 1;

    const int r  = lane & 7;
    const int md = lane >> 3;
    const int arow  = qbase + wm * 16 + (md & 1) * 8 + r;
    const uint32_t abyte = (md >> 1) * 16;
    const int brow0 = wn * 96 + (md >> 1) * 8 + r;
    const uint32_t bbyte = (md & 1) * 16;

    float acc[12][4];
#pragma unroll
    for (int nt = 0; nt < 12; ++nt)
#pragma unroll
        for (int e = 0; e < 4; ++e) acc[nt][e] = 0.f;

#pragma unroll
    for (int ks = 0; ks < 4; ++ks) {
        const uint32_t kb = ks * 32;
        uint32_t ah[4], al[4];
        const uint32_t aoff = sw128((uint32_t)arow * 128u + kb + abyte);
        ldsm_x4(ah[0], ah[1], ah[2], ah[3], sbH + aoff);
        ldsm_x4(al[0], al[1], al[2], al[3], sbL + aoff);
#pragma unroll
        for (int bt = 0; bt < 6; ++bt) {
            uint32_t bh[2][2], bl[2][2];
            const uint32_t boff = sw128((uint32_t)(brow0 + bt * 16) * 128u + kb + bbyte);
            ldsm_x4(bh[0][0], bh[0][1], bh[1][0], bh[1][1], sbH + boff);
            ldsm_x4(bl[0][0], bl[0][1], bl[1][0], bl[1][1], sbL + boff);
#pragma unroll
            for (int p = 0; p < 2; ++p) {
                mma16816(acc[2*bt + p], ah, bh[p]);
                mma16816(acc[2*bt + p], ah, bl[p]);
                mma16816(acc[2*bt + p], al, bh[p]);
            }
        }
    }

    const int quad = lane >> 2;
    const int cp2  = (lane & 3) * 2;
    const int gi0 = i0 + wm * 16 + quad;
    const int gi1 = gi0 + 8;
    const float ni0 = nwin[qbase + wm * 16 + quad];
    const float ni1 = nwin[qbase + wm * 16 + quad + 8];
    const int off0 = (gi0 > WIN) ? (gi0 - WIN) : 0;
    const int off1 = (gi1 > WIN) ? (gi1 - WIN) : 0;
    __half* pr0 = p_buf + (size_t)(h * TT + gi0) * PSTR;
    __half* pr1 = p_buf + (size_t)(h * TT + gi1) * PSTR;
    float ps0 = 0.f, ps1 = 0.f;

#pragma unroll
    for (int nt = 0; nt < 12; ++nt) {
        const int jl = wn * 96 + nt * 8 + cp2;
        const int jg = jstart0 + jl;
        const float nj0 = nwin[jl];
        const float nj1 = nwin[jl + 1];
#pragma unroll
        for (int e = 0; e < 4; ++e) {
            const int  jj = jg + (e & 1);
            const float nj = (e & 1) ? nj1 : nj0;
            const int  gi  = (e >> 1) ? gi1 : gi0;
            const float ni = (e >> 1) ? ni1 : ni0;
            const int  off = (e >> 1) ? off1 : off0;
            if (jj <= gi && jj >= off) {
                float c = acc[nt][e] / (ni * nj + 1e-8f);
                if (c != c) c = 0.f;
                float p = (c + 1.f) * 0.5f;
                ((e >> 1) ? pr1 : pr0)[jj - off] = __float2half_rn(p);
                if (e >> 1) ps1 += p; else ps0 += p;
            }
        }
    }

    ps0 += __shfl_xor_sync(0xffffffffu, ps0, 1);
    ps0 += __shfl_xor_sync(0xffffffffu, ps0, 2);
    ps1 += __shfl_xor_sync(0xffffffffu, ps1, 1);
    ps1 += __shfl_xor_sync(0xffffffffu, ps1, 2);
    if ((lane & 3) == 0) {
        atomicAdd(&rowsum[wm * 16 + quad], ps0);
        atomicAdd(&rowsum[wm * 16 + quad + 8], ps1);
    }
    __syncthreads();

    if (tid < SIT) {
        const int i   = i0 + tid;
        const int cnt = i - ((i > WIN) ? (i - WIN) : 0) + 1;
        float gm = (rowsum[tid] + 0.5f * (float)(TT - cnt)) * (1.f / (float)TT);
        float dn = gm + 0.5f;
        denom_buf[h * TT + i] = dn;
        sinv[tid] = 1.f / dn;
    }
    __syncthreads();
    if (tid < 32) {
        float s = sinv[tid] + sinv[tid + 32];
#pragma unroll
        for (int o = 16; o > 0; o >>= 1) s += __shfl_xor_sync(0xffffffffu, s, o);
        if (tid == 0) atomicAdd(&suminv_buf[h], s);
    }
}

// -------- attn@v via fp16 mma: out = (M·(Vh+Vl) + T·Vh) / (cnt + Σt) --------
// exp(x) = 1 + t with t = x + x²/2 exact to ~6e-10 for x ≤ 1.5e-3.
#define ATTN_SMEM (2 * KP * VSTR * 2 + 2 * 16 * ASTR * 2 + 64)   // 60480

__global__ void __launch_bounds__(256)
k_attnv()
{
    extern __shared__ char dynsm[];
    __half* vh = (__half*)dynsm;                       // [KP][VSTR]
    __half* vl = vh + KP * VSTR;
    __half* tm = vl + KP * VSTR;                       // [16][ASTR]
    __half* mmx = tm + 16 * ASTR;                      // [16][ASTR]
    float* invs = (float*)(mmx + 16 * ASTR);           // [16]

    const int i0  = blockIdx.x * IT;
    const int h   = blockIdx.y;
    const int tid = threadIdx.x;
    const int wid = tid >> 5;
    const int lane = tid & 31;

    const int jstart0 = (i0 > WIN) ? (i0 - WIN) : 0;
    const int span    = (i0 + IT - 1) - jstart0 + 1;   // <= 144 = KP

    // zero-pad v rows [span, KP)
    {
        const int npad = KP - span;
        const uint4 z = make_uint4(0u, 0u, 0u, 0u);
        for (int idx = tid; idx < npad * 11; idx += 256) {
            const int row = span + idx / 11;
            const int q   = idx - (idx / 11) * 11;
            ((uint4*)(vh + row * VSTR))[q] = z;
            ((uint4*)(vl + row * VSTR))[q] = z;
        }
    }

    // v window load + fp16 hi/lo split, row-major (conflict-friendly stores)
    {
        const float4* v4 = (const float4*)v_buf;
        for (int idx = tid; idx < span * 16; idx += 256) {
            const int jj = idx >> 4;
            const int q  = idx & 15;
            float4 v = v4[(size_t)(jstart0 + jj) * (DD / 4) + h * (HDIM / 4) + q];
            __half h0 = __float2half_rn(v.x), h1 = __float2half_rn(v.y),
                   h2 = __float2half_rn(v.z), h3 = __float2half_rn(v.w);
            __half l0 = __float2half_rn(v.x - __half2float(h0)),
                   l1 = __float2half_rn(v.y - __half2float(h1)),
                   l2 = __float2half_rn(v.z - __half2float(h2)),
                   l3 = __float2half_rn(v.w - __half2float(h3));
            __half2* ph = (__half2*)(vh + jj * VSTR);
            __half2* pl = (__half2*)(vl + jj * VSTR);
            ph[q * 2]     = __half2(h0, h1);
            ph[q * 2 + 1] = __half2(h2, h3);
            pl[q * 2]     = __half2(l0, l1);
            pl[q * 2 + 1] = __half2(l2, l3);
        }
    }

    // phase A: build t and mask matrices, compute invs (warp w -> rows w, w+8)
#pragma unroll
    for (int rr = 0; rr < 2; ++rr) {
        const int w = wid + rr * 8;
        const int i = i0 + w;
        const size_t row = (size_t)h * TT + i;
        const float fit  = 1.f / (denom_buf[row] * suminv_buf[h]);
        const int off = ((i > WIN) ? (i - WIN) : 0) - jstart0;
        const int wi  = i - jstart0;
        const int cnt = wi - off + 1;

        float ss = 0.f;
        for (int q = lane; q < KP; q += 32) {
            const bool in = (q >= off) && (q <= wi);
            float x = in ? fit * __half2float(p_buf[row * PSTR + (q - off)]) : 0.f;
            float t = fmaf(0.5f * x, x, x);           // exp(x)-1 to ~6e-10
            tm[w * ASTR + q]  = __float2half_rn(t);   // 0 outside window
            mmx[w * ASTR + q] = __float2half_rn(in ? 1.f : 0.f);
            ss += t;
        }
#pragma unroll
        for (int o = 16; o > 0; o >>= 1) ss += __shfl_xor_sync(0xffffffffu, ss, o);
        if (lane == 0) invs[w] = 1.f / ((float)cnt + ss);
    }
    __syncthreads();

    // phase B: per-warp n8 tile via mma; A = mask/t [16xK], B = V^T via ldsm.trans
    {
        const uint32_t bvh = s2u(vh), bvl = s2u(vl);
        const uint32_t btm = s2u(tm), bmm = s2u(mmx);
        const int r  = lane & 7;
        const int md = lane >> 3;
        const uint32_t aoff = (uint32_t)(r + (md & 1) * 8) * (ASTR * 2) + (md >> 1) * 16;
        const int bl15 = lane & 15;

        float am[4] = {0.f, 0.f, 0.f, 0.f};
        float at[4] = {0.f, 0.f, 0.f, 0.f};

#pragma unroll
        for (int ks = 0; ks < KP / 16; ++ks) {        // 9 k-steps
            uint32_t amk[4], atk[4];
            ldsm_x4(amk[0], amk[1], amk[2], amk[3], bmm + aoff + ks * 32);
            ldsm_x4(atk[0], atk[1], atk[2], atk[3], btm + aoff + ks * 32);
            const uint32_t baddr = (uint32_t)(ks * 16 + bl15) * (VSTR * 2) + wid * 16;
            uint32_t bh[2], bl[2];
            ldsm_x2_trans(bh[0], bh[1], bvh + baddr);
            ldsm_x2_trans(bl[0], bl[1], bvl + baddr);
            mma16816h(am, amk, bh);
            mma16816h(am, amk, bl);
            mma16816h(at, atk, bh);
        }

        // epilogue: D layout row = lane>>2 (+8), col = (lane&3)*2 (+1)
        const int row0 = lane >> 2;
        const int c    = (lane & 3) * 2;
        const int colg = h * HDIM + wid * 8 + c;
#pragma unroll
        for (int half_ = 0; half_ < 2; ++half_) {
            const int rw  = row0 + half_ * 8;
            const float iv = invs[rw];
            const float v0 = (am[half_ * 2 + 0] + at[half_ * 2 + 0]) * iv;
            const float v1 = (am[half_ * 2 + 1] + at[half_ * 2 + 1]) * iv;
            const size_t idx = (size_t)(i0 + rw) * DD + colg;
            __half h0 = __float2half_rn(v0), h1 = __float2half_rn(v1);
            __half l0 = __float2half_rn(v0 - __half2float(h0));
            __half l1 = __float2half_rn(v1 - __half2float(h1));
            *(__half2*)(oh_buf + idx) = __half2(h0, h1);
            *(__half2*)(ol_buf + idx) = __half2(l0, l1);
        }
    }
}

// ---------------- launch ---------------------------------------------------
extern "C" void kernel_launch(void* const* d_in, const int* in_sizes, int n_in,
                              void* d_out, int out_size)
{
    const float* x  = (const float*)d_in[0];
    const float* Wg = (const float*)d_in[1];
    const float* bg = (const float*)d_in[2];
    const float* Wv = (const float*)d_in[3];
    const float* bv = (const float*)d_in[4];
    const float* Wo = (const float*)d_in[5];
    const float* bo = (const float*)d_in[6];
    float* out = (float*)d_out;

    cudaFuncSetAttribute(k_gemm_gv,   cudaFuncAttributeMaxDynamicSharedMemorySize, SMEM_G);
    cudaFuncSetAttribute(k_gemm_o,    cudaFuncAttributeMaxDynamicSharedMemorySize, SMEM_G);
    cudaFuncSetAttribute(k_scores_mma,cudaFuncAttributeMaxDynamicSharedMemorySize, SMEM_S);
    cudaFuncSetAttribute(k_attnv,     cudaFuncAttributeMaxDynamicSharedMemorySize, ATTN_SMEM);

    k_conv_all<<<2560, 256>>>(x, Wg, Wv, Wo);                 // #1

    dim3 gemm_gv(DD / 128, TT / 128, 2);                      // 256 CTAs = 1 wave
    k_gemm_gv<<<gemm_gv, 256, SMEM_G>>>(bg, bv);              // #2

    dim3 sc_grid(TT / SIT, NH);
    k_scores_mma<<<sc_grid, 256, SMEM_S>>>();                 // #3

    dim3 av_grid(TT / IT, NH);                                // 2048 blocks
    k_attnv<<<av_grid, 256, ATTN_SMEM>>>();                   // #4 (ncu slot)

    dim3 gemm_o(DD / 128, TT / 128, 1);                       // 128 CTAs = 1 wave
    k_gemm_o<<<gemm_o, 256, SMEM_G>>>(bo, out);               // #5
}